// round 15
// baseline (speedup 1.0000x reference)
#include <cuda_runtime.h>
#include <cuda_bf16.h>
#include <cstdint>

#define N_NODES  100000
#define N_EDGES  1600000
#define N_GRAPHS 50
#define FDIM     128

// Scratch
__device__ __align__(128) float g_agg[2][(size_t)N_NODES * FDIM];
__device__ __align__(128) float g_gproj[N_GRAPHS * FDIM];
__device__ __align__(128) __nv_bfloat16 g_Whi[3 * FDIM * FDIM];
__device__ __align__(128) __nv_bfloat16 g_Wlo[3 * FDIM * FDIM];

// ---------------------------------------------------------------------------
// helpers
// ---------------------------------------------------------------------------
__device__ __forceinline__ unsigned smem_u32(const void* p) {
    unsigned a;
    asm("{ .reg .u64 t; cvta.to.shared.u64 t, %1; cvt.u32.u64 %0, t; }"
        : "=r"(a) : "l"(p));
    return a;
}
__device__ __forceinline__ unsigned pbf2(float lo, float hi) {
    unsigned r;
    asm("cvt.rn.bf16x2.f32 %0, %1, %2;" : "=r"(r) : "f"(hi), "f"(lo));
    return r;
}
__device__ __forceinline__ void ldsm4(unsigned* r, unsigned addr) {
    asm volatile("ldmatrix.sync.aligned.m8n8.x4.shared.b16 {%0,%1,%2,%3}, [%4];"
                 : "=r"(r[0]), "=r"(r[1]), "=r"(r[2]), "=r"(r[3]) : "r"(addr));
}
__device__ __forceinline__ void mma_bf16(float* c, const unsigned* a,
                                         const unsigned* b) {
    asm volatile(
        "mma.sync.aligned.m16n8k16.row.col.f32.bf16.bf16.f32 "
        "{%0,%1,%2,%3}, {%4,%5,%6,%7}, {%8,%9}, {%0,%1,%2,%3};"
        : "+f"(c[0]), "+f"(c[1]), "+f"(c[2]), "+f"(c[3])
        : "r"(a[0]), "r"(a[1]), "r"(a[2]), "r"(a[3]), "r"(b[0]), "r"(b[1]));
}

// ---------------------------------------------------------------------------
// Zero the aggregation buffers
// ---------------------------------------------------------------------------
__global__ void zero_kernel() {
    size_t n = ((size_t)2 * N_NODES * FDIM) / 4;
    float4* p = (float4*)g_agg;
    float4 z = make_float4(0.f, 0.f, 0.f, 0.f);
    for (size_t i = (size_t)blockIdx.x * blockDim.x + threadIdx.x; i < n;
         i += (size_t)gridDim.x * blockDim.x)
        p[i] = z;
}

// ---------------------------------------------------------------------------
// Split weights into bf16 hi/lo
// ---------------------------------------------------------------------------
__global__ void wsplit_kernel(const float* __restrict__ Wn,
                              const float* __restrict__ Wi,
                              const float* __restrict__ Wo) {
    int i = blockIdx.x * blockDim.x + threadIdx.x;
    if (i >= 3 * FDIM * FDIM) return;
    const float* W[3] = {Wn, Wi, Wo};
    float w = W[i >> 14][i & 16383];
    __nv_bfloat16 h = __float2bfloat16_rn(w);
    g_Whi[i] = h;
    g_Wlo[i] = __float2bfloat16_rn(w - __bfloat162float(h));
}

// ---------------------------------------------------------------------------
// Project globals: g_gproj[g][j] = dot(G[g], Wg[j]) + bias[j]  (fp32 exact)
// ---------------------------------------------------------------------------
__global__ void gproj_kernel(const float* __restrict__ gf,
                             const float* __restrict__ Wg,
                             const float* __restrict__ bias) {
    __shared__ float s[FDIM];
    int g = blockIdx.x, j = threadIdx.x;
    s[j] = gf[g * FDIM + j];
    __syncthreads();
    const float4* wrow = (const float4*)(Wg + (size_t)j * FDIM);
    float acc = 0.f;
#pragma unroll
    for (int k = 0; k < FDIM / 4; k++) {
        float4 w = wrow[k];
        const float4 a = *(const float4*)&s[k * 4];
        acc += a.x * w.x + a.y * w.y + a.z * w.z + a.w * w.w;
    }
    g_gproj[g * FDIM + j] = acc + bias[j];
}

// ---------------------------------------------------------------------------
// Column-split scatter (R14 WIN)
// ---------------------------------------------------------------------------
__global__ void scatter_half_kernel(const float4* __restrict__ ef,
                                    const int* __restrict__ recv,
                                    const int* __restrict__ send,
                                    int half) {
    long long gtid = (long long)blockIdx.x * blockDim.x + threadIdx.x;
    int e = (int)(gtid >> 4);
    if (e >= N_EDGES) return;
    int l = threadIdx.x & 15;

    unsigned long long pol_last, pol_first;
    asm("createpolicy.fractional.L2::evict_last.b64 %0, 1.0;" : "=l"(pol_last));
    asm("createpolicy.fractional.L2::evict_first.b64 %0, 1.0;" : "=l"(pol_first));

    float4 v;
    asm volatile("ld.global.nc.L2::cache_hint.v4.f32 {%0,%1,%2,%3}, [%4], %5;"
                 : "=f"(v.x), "=f"(v.y), "=f"(v.z), "=f"(v.w)
                 : "l"(&ef[(size_t)e * (FDIM / 4) + half * 16 + l]),
                   "l"(pol_first));
    int r = __ldg(&recv[e]);
    int s = __ldg(&send[e]);
    const int coff = half * 64 + l * 4;
    float* pr = &g_agg[0][(size_t)r * FDIM + coff];
    float* ps = &g_agg[1][(size_t)s * FDIM + coff];
    asm volatile("red.global.add.L2::cache_hint.v4.f32 [%0], {%1,%2,%3,%4}, %5;"
                 :: "l"(pr), "f"(v.x), "f"(v.y), "f"(v.z), "f"(v.w), "l"(pol_last)
                 : "memory");
    asm volatile("red.global.add.L2::cache_hint.v4.f32 [%0], {%1,%2,%3,%4}, %5;"
                 :: "l"(ps), "f"(v.x), "f"(v.y), "f"(v.z), "f"(v.w), "l"(pol_last)
                 : "memory");
}

// ---------------------------------------------------------------------------
// mma.sync bf16 split-3 GEMM, phase-persistent B + double-buffered A.
// Dynamic smem 96KB: B hi [4 x 8KB] | B lo [4 x 8KB] | A buf[2] x (hi+lo 16KB).
// ---------------------------------------------------------------------------
#define TOFF(r, kk) (((r) >> 3) * 512 + ((kk) >> 3) * 128 + ((r)&7) * 16 + ((kk)&7) * 2)
#define SM_B_LO 32768
#define SM_A    65536
#define GEMM_SMEM 98304

__global__ __launch_bounds__(256, 2) void gemm_kernel(
    const float* __restrict__ node,
    const int* __restrict__ gidx,
    float* __restrict__ out) {
    extern __shared__ __align__(128) unsigned char sm[];
    const unsigned sBase = smem_u32(sm);

    const int tid = threadIdx.x;
    const int wid = tid >> 5, lid = tid & 31;
    const int wm = wid & 3, wn = wid >> 2;
    const int m0 = blockIdx.x * 128;

    const int t8 = lid >> 3, r8 = lid & 7;
    const unsigned aOff = (unsigned)TOFF(wm * 32 + (t8 & 1) * 8 + r8, (t8 >> 1) * 8);
    const unsigned bOff = (unsigned)TOFF(wn * 64 + (t8 >> 1) * 8 + r8, (t8 & 1) * 8);

    float acc[2][8][4];
#pragma unroll
    for (int i = 0; i < 2; i++)
#pragma unroll
        for (int j = 0; j < 8; j++)
#pragma unroll
            for (int q = 0; q < 4; q++) acc[i][j][q] = 0.f;

    const float* Asrc[3] = {node, g_agg[0], g_agg[1]};

    const int frow = tid >> 1;
    const int fh   = tid & 1;
    const int fkh  = fh * 16;
    int arow_g = m0 + frow;
    if (arow_g >= N_NODES) arow_g = N_NODES - 1;

    const unsigned aso0 = (unsigned)((frow >> 3) * 512 + (fkh >> 3) * 128 +
                                     (frow & 7) * 16);
    const unsigned aso1 = aso0 + 128;

    float4 fa[4];

#define LDG_A(PH, C)                                                          \
    {                                                                         \
        const float* ap_ = Asrc[PH] + (size_t)arow_g * FDIM + (C)*32 + fkh;   \
        fa[0] = *(const float4*)(ap_);                                        \
        fa[1] = *(const float4*)(ap_ + 4);                                    \
        fa[2] = *(const float4*)(ap_ + 8);                                    \
        fa[3] = *(const float4*)(ap_ + 12);                                   \
    }

#define ST_A(BUF)                                                             \
    {                                                                         \
        unsigned base_ = SM_A + (unsigned)(BUF)*16384;                        \
        _Pragma("unroll") for (int g = 0; g < 2; g++) {                       \
            float4 f0 = fa[g * 2], f1 = fa[g * 2 + 1];                        \
            __nv_bfloat16 h0 = __float2bfloat16_rn(f0.x);                     \
            __nv_bfloat16 h1 = __float2bfloat16_rn(f0.y);                     \
            __nv_bfloat16 h2 = __float2bfloat16_rn(f0.z);                     \
            __nv_bfloat16 h3 = __float2bfloat16_rn(f0.w);                     \
            __nv_bfloat16 h4 = __float2bfloat16_rn(f1.x);                     \
            __nv_bfloat16 h5 = __float2bfloat16_rn(f1.y);                     \
            __nv_bfloat16 h6 = __float2bfloat16_rn(f1.z);                     \
            __nv_bfloat16 h7 = __float2bfloat16_rn(f1.w);                     \
            uint4 vh;                                                         \
            vh.x = ((unsigned)__bfloat16_as_ushort(h1) << 16) |               \
                   __bfloat16_as_ushort(h0);                                  \
            vh.y = ((unsigned)__bfloat16_as_ushort(h3) << 16) |               \
                   __bfloat16_as_ushort(h2);                                  \
            vh.z = ((unsigned)__bfloat16_as_ushort(h5) << 16) |               \
                   __bfloat16_as_ushort(h4);                                  \
            vh.w = ((unsigned)__bfloat16_as_ushort(h7) << 16) |               \
                   __bfloat16_as_ushort(h6);                                  \
            uint4 vl;                                                         \
            vl.x = pbf2(f0.x - __bfloat162float(h0), f0.y - __bfloat162float(h1)); \
            vl.y = pbf2(f0.z - __bfloat162float(h2), f0.w - __bfloat162float(h3)); \
            vl.z = pbf2(f1.x - __bfloat162float(h4), f1.y - __bfloat162float(h5)); \
            vl.w = pbf2(f1.z - __bfloat162float(h6), f1.w - __bfloat162float(h7)); \
            unsigned off_ = base_ + (g ? aso1 : aso0);                        \
            *(uint4*)(sm + off_) = vh;                                        \
            *(uint4*)(sm + off_ + 8192) = vl;                                 \
        }                                                                     \
    }

#pragma unroll 1
    for (int ph = 0; ph < 3; ph++) {
        __syncthreads();  // previous phase's mma reads complete before B overwrite
        {
            const unsigned char* bh = (const unsigned char*)g_Whi +
                ((size_t)ph * FDIM * FDIM + (size_t)frow * FDIM + fh * 64) * 2;
            const unsigned char* bl = (const unsigned char*)g_Wlo +
                ((size_t)ph * FDIM * FDIM + (size_t)frow * FDIM + fh * 64) * 2;
#pragma unroll
            for (int q = 0; q < 8; q++) {
                int col = fh * 64 + q * 8;
                unsigned dst = (unsigned)((col >> 5) * 8192 + TOFF(frow, (col & 31)));
                *(uint4*)(sm + dst) = *(const uint4*)(bh + q * 16);
                *(uint4*)(sm + SM_B_LO + dst) = *(const uint4*)(bl + q * 16);
            }
        }
        LDG_A(ph, 0);
        ST_A(0);
        __syncthreads();

#pragma unroll 1
        for (int c = 0; c < 4; c++) {
            if (c < 3) LDG_A(ph, c + 1);

            const unsigned aHi = sBase + SM_A + (unsigned)(c & 1) * 16384 + aOff;
            const unsigned bB  = sBase + (unsigned)c * 8192 + bOff;
#pragma unroll
            for (int ks = 0; ks < 2; ks++) {
                const unsigned kso = ks * 256;
                unsigned ah[2][4], al[2][4];
                ldsm4(ah[0], aHi + kso);
                ldsm4(ah[1], aHi + 1024 + kso);
                ldsm4(al[0], aHi + 8192 + kso);
                ldsm4(al[1], aHi + 9216 + kso);
#pragma unroll
                for (int np = 0; np < 4; np++) {
                    unsigned bh[4], bl[4];
                    ldsm4(bh, bB + np * 1024 + kso);
                    ldsm4(bl, bB + SM_B_LO + np * 1024 + kso);
#pragma unroll
                    for (int mt = 0; mt < 2; mt++) {
                        mma_bf16(acc[mt][np * 2], ah[mt], bh);
                        mma_bf16(acc[mt][np * 2 + 1], ah[mt], bh + 2);
                        mma_bf16(acc[mt][np * 2], ah[mt], bl);
                        mma_bf16(acc[mt][np * 2 + 1], ah[mt], bl + 2);
                        mma_bf16(acc[mt][np * 2], al[mt], bh);
                        mma_bf16(acc[mt][np * 2 + 1], al[mt], bh + 2);
                    }
                }
            }
            if (c < 3) {
                __syncthreads();
                ST_A((c + 1) & 1);
                __syncthreads();
            }
        }
    }
#undef LDG_A
#undef ST_A

    const int quad = lid >> 2, qlane = lid & 3;
#pragma unroll
    for (int mt = 0; mt < 2; mt++) {
        const int r0 = m0 + wm * 32 + mt * 16 + quad;
        const int r1 = r0 + 8;
        const bool ok0 = r0 < N_NODES, ok1 = r1 < N_NODES;
        const float* gp0 = g_gproj + (size_t)(ok0 ? __ldg(&gidx[r0]) : 0) * FDIM;
        const float* gp1 = g_gproj + (size_t)(ok1 ? __ldg(&gidx[r1]) : 0) * FDIM;
#pragma unroll
        for (int nt = 0; nt < 8; nt++) {
            const int col = wn * 64 + nt * 8 + qlane * 2;
            if (ok0) {
                float2 g0 = *(const float2*)(gp0 + col);
                float2 o0 = make_float2(acc[mt][nt][0] + g0.x, acc[mt][nt][1] + g0.y);
                *(float2*)(out + (size_t)r0 * FDIM + col) = o0;
            }
            if (ok1) {
                float2 g1 = *(const float2*)(gp1 + col);
                float2 o1 = make_float2(acc[mt][nt][2] + g1.x, acc[mt][nt][3] + g1.y);
                *(float2*)(out + (size_t)r1 * FDIM + col) = o1;
            }
        }
    }
}

// ---------------------------------------------------------------------------
// Launch
// ---------------------------------------------------------------------------
extern "C" void kernel_launch(void* const* d_in, const int* in_sizes, int n_in,
                              void* d_out, int out_size) {
    const float* node_features   = (const float*)d_in[0];
    const float* edge_features   = (const float*)d_in[1];
    const float* global_features = (const float*)d_in[2];
    const float* W_node     = (const float*)d_in[3];
    const float* W_incoming = (const float*)d_in[4];
    const float* W_outgoing = (const float*)d_in[5];
    const float* W_global   = (const float*)d_in[6];
    const float* bias       = (const float*)d_in[7];
    const int*   receivers  = (const int*)d_in[8];
    const int*   senders    = (const int*)d_in[9];
    const int*   graph_idx  = (const int*)d_in[10];
    float* out = (float*)d_out;

    cudaFuncSetAttribute(gemm_kernel,
                         cudaFuncAttributeMaxDynamicSharedMemorySize,
                         GEMM_SMEM);

    zero_kernel<<<1024, 256>>>();
    wsplit_kernel<<<(3 * FDIM * FDIM + 255) / 256, 256>>>(W_node, W_incoming,
                                                          W_outgoing);
    gproj_kernel<<<N_GRAPHS, FDIM>>>(global_features, W_global, bias);

    {
        int threads = 256;
        long long total = (long long)N_EDGES * 16;
        int blocks = (int)((total + threads - 1) / threads);
        scatter_half_kernel<<<blocks, threads>>>((const float4*)edge_features,
                                                 receivers, senders, 0);
        scatter_half_kernel<<<blocks, threads>>>((const float4*)edge_features,
                                                 receivers, senders, 1);
    }
    {
        int grid = (N_NODES + 127) / 128;  // 782
        gemm_kernel<<<grid, 256, GEMM_SMEM>>>(node_features, graph_idx, out);
    }
}